// round 2
// baseline (speedup 1.0000x reference)
#include <cuda_runtime.h>

#define DIM 64
#define MAX_NODES 100000

typedef unsigned long long ull;

// Aggregation buffer: h = x + segment_sum(msg). Re-initialized every call.
__device__ __align__(16) float g_h[MAX_NODES * DIM];

__device__ __forceinline__ ull pk2(float lo, float hi) {
    ull r;
    asm("mov.b64 %0, {%1, %2};" : "=l"(r) : "f"(lo), "f"(hi));
    return r;
}
__device__ __forceinline__ void upk2(float& lo, float& hi, ull v) {
    asm("mov.b64 {%0, %1}, %2;" : "=f"(lo), "=f"(hi) : "l"(v));
}
// Blackwell packed fp32x2 FMA: d.x += a.x*b.x; d.y += a.y*b.y
__device__ __forceinline__ void ffma2(ull& d, ull a, ull b) {
    asm("fma.rn.f32x2 %0, %1, %2, %0;" : "+l"(d) : "l"(a), "l"(b));
}

// ---------------------------------------------------------------------------
// Kernel 0: g_h = x   (h starts at x, scatter adds on top)
// ---------------------------------------------------------------------------
__global__ void init_h_kernel(const float4* __restrict__ x4, int n4) {
    int i = blockIdx.x * blockDim.x + threadIdx.x;
    if (i < n4) reinterpret_cast<float4*>(g_h)[i] = x4[i];
}

// ---------------------------------------------------------------------------
// Kernel 1: per-edge  e = ea@We + be ; msg = relu(x[src]+e) ; red-add to g_h[dst]
// One warp per edge (grid-stride). Lane l owns output cols (2l, 2l+1).
// K dimension (16) processed as 8 packed pairs with fp32x2 FMA.
// Scatter: even lanes issue red.global.add.v4.f32 (4 cols per red).
// edge_index is INT32 (JAX default x64-disabled downcasts int64 -> int32).
// ---------------------------------------------------------------------------
__global__ void __launch_bounds__(256) edge_kernel(
    const float* __restrict__ x,
    const int* __restrict__ ei,         // [2, E] int32
    const float4* __restrict__ ea4,     // [E, 16] as float4
    const float* __restrict__ We,       // [16, 64]
    const float* __restrict__ be,       // [64]
    int E)
{
    const int lane = threadIdx.x & 31;
    const int c0 = lane * 2;
    int warp = (blockIdx.x * blockDim.x + threadIdx.x) >> 5;
    const int nwarps = (gridDim.x * blockDim.x) >> 5;

    // Hoist W_edge pairs into registers (reused across all edges of this warp).
    ull wA[8], wB[8];
#pragma unroll
    for (int k2 = 0; k2 < 8; k2++) {
        wA[k2] = pk2(We[(2 * k2) * DIM + c0],     We[(2 * k2 + 1) * DIM + c0]);
        wB[k2] = pk2(We[(2 * k2) * DIM + c0 + 1], We[(2 * k2 + 1) * DIM + c0 + 1]);
    }
    const float be0 = be[c0], be1 = be[c0 + 1];

    for (int e = warp; e < E; e += nwarps) {
        const int src = ei[e];
        const int dst = ei[E + e];

        // 16 edge features, broadcast to all lanes (same address -> L1 broadcast)
        const float4 q0 = ea4[e * 4 + 0];
        const float4 q1 = ea4[e * 4 + 1];
        const float4 q2 = ea4[e * 4 + 2];
        const float4 q3 = ea4[e * 4 + 3];
        ull a[8];
        a[0] = pk2(q0.x, q0.y); a[1] = pk2(q0.z, q0.w);
        a[2] = pk2(q1.x, q1.y); a[3] = pk2(q1.z, q1.w);
        a[4] = pk2(q2.x, q2.y); a[5] = pk2(q2.z, q2.w);
        a[6] = pk2(q3.x, q3.y); a[7] = pk2(q3.z, q3.w);

        ull accA = 0ull, accB = 0ull;   // bit pattern 0 == {+0.f, +0.f}
#pragma unroll
        for (int k2 = 0; k2 < 8; k2++) {
            ffma2(accA, a[k2], wA[k2]);
            ffma2(accB, a[k2], wB[k2]);
        }

        // gather x[src] (coalesced: 32 lanes cover the 256B row)
        const float2 xv = *reinterpret_cast<const float2*>(x + (size_t)src * DIM + c0);

        float aLo, aHi, bLo, bHi;
        upk2(aLo, aHi, accA);
        upk2(bLo, bHi, accB);
        float m0 = fmaxf(xv.x + (aLo + aHi + be0), 0.f);
        float m1 = fmaxf(xv.y + (bLo + bHi + be1), 0.f);

        // combine with neighbor lane -> one v4 red per 4 columns
        const float m2 = __shfl_down_sync(0xFFFFFFFFu, m0, 1);
        const float m3 = __shfl_down_sync(0xFFFFFFFFu, m1, 1);
        if (!(lane & 1)) {
            float* p = g_h + (size_t)dst * DIM + c0;  // 16B aligned (c0 % 4 == 0 on even lanes)
            asm volatile("red.global.add.v4.f32 [%0], {%1, %2, %3, %4};"
                         :: "l"(p), "f"(m0), "f"(m1), "f"(m2), "f"(m3)
                         : "memory");
        }
    }
}

// ---------------------------------------------------------------------------
// Kernel 2: out = relu(h@W1 + b1) @ W2 + b2
// 128 nodes per block, 256 threads, 8x4 register tiles, fp32x2 packed FMA
// over K pairs. W staged in shared as packed (2k,2k+1) pairs; re-staged
// between the two layers. t written back into the h tile.
// ---------------------------------------------------------------------------
#define HS_LD 68                               // row pitch (floats): 16B aligned rows
#define MLP_SMEM (128 * HS_LD * 4 + 32 * 64 * 8)

__global__ void __launch_bounds__(256) mlp_kernel(
    const float* __restrict__ W1, const float* __restrict__ b1,
    const float* __restrict__ W2, const float* __restrict__ b2,
    float* __restrict__ out, int N)
{
    extern __shared__ float smem[];
    float* hs = smem;                          // [128][HS_LD]
    ull*   Wp = reinterpret_cast<ull*>(smem + 128 * HS_LD);  // [32][64] packed K-pairs

    const int tid = threadIdx.x;
    const int nb = blockIdx.x * 128;

    // stage h tile (zeros past N)
#pragma unroll
    for (int f = tid; f < 128 * 16; f += 256) {
        const int i = f >> 4, c4 = f & 15;
        float4 v = make_float4(0.f, 0.f, 0.f, 0.f);
        if (nb + i < N) v = reinterpret_cast<const float4*>(g_h)[(size_t)(nb + i) * 16 + c4];
        *reinterpret_cast<float4*>(hs + i * HS_LD + c4 * 4) = v;
    }
    // stage W1 pairs
    for (int f = tid; f < 2048; f += 256) {
        const int k2 = f >> 6, j = f & 63;
        Wp[f] = pk2(W1[(2 * k2) * DIM + j], W1[(2 * k2 + 1) * DIM + j]);
    }
    __syncthreads();

    const int rg = tid >> 4, jg = tid & 15;
    const int i0 = rg * 8, j0 = jg * 4;

    float t[8][4];

    // ---- layer 1 ----
    {
        ull acc[8][4];
#pragma unroll
        for (int ii = 0; ii < 8; ii++)
#pragma unroll
            for (int jj = 0; jj < 4; jj++) acc[ii][jj] = 0ull;

#pragma unroll 8
        for (int k2 = 0; k2 < 32; k2++) {
            ull hv[8];
#pragma unroll
            for (int ii = 0; ii < 8; ii++)
                hv[ii] = *reinterpret_cast<const ull*>(hs + (i0 + ii) * HS_LD + 2 * k2);
            const ulonglong2 w01 = *reinterpret_cast<const ulonglong2*>(Wp + k2 * 64 + j0);
            const ulonglong2 w23 = *reinterpret_cast<const ulonglong2*>(Wp + k2 * 64 + j0 + 2);
            ull wv[4] = { w01.x, w01.y, w23.x, w23.y };
#pragma unroll
            for (int ii = 0; ii < 8; ii++)
#pragma unroll
                for (int jj = 0; jj < 4; jj++) ffma2(acc[ii][jj], hv[ii], wv[jj]);
        }
        const float4 bb = *reinterpret_cast<const float4*>(b1 + j0);
        const float bbv[4] = { bb.x, bb.y, bb.z, bb.w };
#pragma unroll
        for (int ii = 0; ii < 8; ii++)
#pragma unroll
            for (int jj = 0; jj < 4; jj++) {
                float lo, hi;
                upk2(lo, hi, acc[ii][jj]);
                t[ii][jj] = fmaxf(lo + hi + bbv[jj], 0.f);
            }
    }
    __syncthreads();   // all reads of hs/Wp done

    // write t back into hs, re-stage W2
#pragma unroll
    for (int ii = 0; ii < 8; ii++)
        *reinterpret_cast<float4*>(hs + (i0 + ii) * HS_LD + j0) =
            make_float4(t[ii][0], t[ii][1], t[ii][2], t[ii][3]);
    for (int f = tid; f < 2048; f += 256) {
        const int k2 = f >> 6, j = f & 63;
        Wp[f] = pk2(W2[(2 * k2) * DIM + j], W2[(2 * k2 + 1) * DIM + j]);
    }
    __syncthreads();

    // ---- layer 2 ----
    {
        ull acc[8][4];
#pragma unroll
        for (int ii = 0; ii < 8; ii++)
#pragma unroll
            for (int jj = 0; jj < 4; jj++) acc[ii][jj] = 0ull;

#pragma unroll 8
        for (int k2 = 0; k2 < 32; k2++) {
            ull hv[8];
#pragma unroll
            for (int ii = 0; ii < 8; ii++)
                hv[ii] = *reinterpret_cast<const ull*>(hs + (i0 + ii) * HS_LD + 2 * k2);
            const ulonglong2 w01 = *reinterpret_cast<const ulonglong2*>(Wp + k2 * 64 + j0);
            const ulonglong2 w23 = *reinterpret_cast<const ulonglong2*>(Wp + k2 * 64 + j0 + 2);
            ull wv[4] = { w01.x, w01.y, w23.x, w23.y };
#pragma unroll
            for (int ii = 0; ii < 8; ii++)
#pragma unroll
                for (int jj = 0; jj < 4; jj++) ffma2(acc[ii][jj], hv[ii], wv[jj]);
        }
        const float4 bb = *reinterpret_cast<const float4*>(b2 + j0);
        const float bbv[4] = { bb.x, bb.y, bb.z, bb.w };
#pragma unroll
        for (int ii = 0; ii < 8; ii++) {
            const int n = nb + i0 + ii;
            if (n < N) {
                float r[4];
#pragma unroll
                for (int jj = 0; jj < 4; jj++) {
                    float lo, hi;
                    upk2(lo, hi, acc[ii][jj]);
                    r[jj] = lo + hi + bbv[jj];
                }
                *reinterpret_cast<float4*>(out + (size_t)n * DIM + j0) =
                    make_float4(r[0], r[1], r[2], r[3]);
            }
        }
    }
}

// ---------------------------------------------------------------------------
extern "C" void kernel_launch(void* const* d_in, const int* in_sizes, int n_in,
                              void* d_out, int out_size)
{
    const float* x  = (const float*)d_in[0];
    const int*   ei = (const int*)d_in[1];        // int32 (JAX x64 disabled)
    const float* ea = (const float*)d_in[2];
    const float* We = (const float*)d_in[3];
    const float* be = (const float*)d_in[4];
    const float* W1 = (const float*)d_in[5];
    const float* b1 = (const float*)d_in[6];
    const float* W2 = (const float*)d_in[7];
    const float* b2 = (const float*)d_in[8];
    float* out = (float*)d_out;

    const int N = in_sizes[0] / DIM;       // 100000
    const int E = in_sizes[1] / 2;         // 1600000

    // 0) h = x
    const int n4 = N * (DIM / 4);
    init_h_kernel<<<(n4 + 255) / 256, 256>>>(reinterpret_cast<const float4*>(x), n4);

    // 1) edge scatter
    edge_kernel<<<1776, 256>>>(x, ei, reinterpret_cast<const float4*>(ea), We, be, E);

    // 2) node MLP
    cudaFuncSetAttribute(mlp_kernel, cudaFuncAttributeMaxDynamicSharedMemorySize, MLP_SMEM);
    mlp_kernel<<<(N + 127) / 128, 256, MLP_SMEM>>>(W1, b1, W2, b2, out, N);
}